// round 10
// baseline (speedup 1.0000x reference)
#include <cuda_runtime.h>
#include <cuda_bf16.h>
#include <cstdint>

typedef unsigned long long u64;

constexpr int D = 128;
constexpr int K = 32;
constexpr int H = 32;
constexpr int O = 128;
constexpr int G = 4;                 // nodes per CTA (1 per warp)
constexpr int NTHREADS = 128;

constexpr int ASTRIDE = 272;         // bytes per tile row (128 bf16 + 8 pad) — conflict-free ldmatrix
constexpr int ATILE   = 32 * ASTRIDE;  // 8704 B per 32x128 bf16 tile

// ---- dynamic smem layout (bytes, all 16B aligned) ----
constexpr uint32_t OFF_AHI = 0;                     // 4 warps x 8704
constexpr uint32_t OFF_ALO = OFF_AHI + 4 * ATILE;   // 4 x 8704
constexpr uint32_t OFF_BHI = OFF_ALO + 4 * ATILE;   // W1^T hi tile 8704
constexpr uint32_t OFF_BLO = OFF_BHI + ATILE;       // W1^T lo tile 8704
constexpr uint32_t OFF_W2  = OFF_BLO + ATILE;       // 32*33*4 = 4224
constexpr uint32_t OFF_X   = OFF_W2 + 4224;         // 4*32 float4 = 2048
constexpr uint32_t OFF_AGG = OFF_X + 2048;          // 2048
constexpr uint32_t OFF_U   = OFF_AGG + 2048;        // 512
constexpr uint32_t OFF_T   = OFF_U + 512;           // 512
constexpr uint32_t SMEM_BYTES = OFF_T + 512;        // 96384

// ---- persistent repacked weights ----
__device__ ulonglong2 g_W1q[32 * 32];     // fp32-packed W1 for exact u path
__device__ float4     g_BThi4[ATILE / 16];  // W1^T bf16 hi, padded image
__device__ float4     g_BTlo4[ATILE / 16];  // W1^T bf16 lo
__device__ float4     g_Wn4[32 * 128];    // [q][col] = W_node[4q..4q+3][col]
__device__ float4     g_Wb4[32 * 128];

// ---- helpers ----
__device__ __forceinline__ u64 pack2(float lo, float hi) {
    u64 r; asm("mov.b64 %0, {%1, %2};" : "=l"(r) : "f"(lo), "f"(hi)); return r;
}
__device__ __forceinline__ float2 unpack2(u64 v) {
    float2 f; asm("mov.b64 {%0, %1}, %2;" : "=f"(f.x), "=f"(f.y) : "l"(v)); return f;
}
__device__ __forceinline__ u64 ffma2(u64 a, u64 b, u64 c) {
    u64 d; asm("fma.rn.f32x2 %0, %1, %2, %3;" : "=l"(d) : "l"(a), "l"(b), "l"(c)); return d;
}
__device__ __forceinline__ float fc(const float4& v, int i) {
    return i == 0 ? v.x : (i == 1 ? v.y : (i == 2 ? v.z : v.w));
}
__device__ __forceinline__ uint32_t smem_u32(const void* p) {
    uint32_t a;
    asm("{ .reg .u64 t; cvta.to.shared.u64 t, %1; cvt.u32.u64 %0, t; }" : "=r"(a) : "l"(p));
    return a;
}
__device__ __forceinline__ float ftanh(float x) {
    float e = __expf(2.0f * x);
    return 1.0f - __fdividef(2.0f, e + 1.0f);
}
__device__ __forceinline__ void ldsm4(uint32_t& r0, uint32_t& r1, uint32_t& r2, uint32_t& r3,
                                      uint32_t addr) {
    asm volatile("ldmatrix.sync.aligned.m8n8.x4.shared.b16 {%0,%1,%2,%3}, [%4];"
                 : "=r"(r0), "=r"(r1), "=r"(r2), "=r"(r3) : "r"(addr));
}
__device__ __forceinline__ void mma16816(float* d, uint32_t a0, uint32_t a1, uint32_t a2,
                                         uint32_t a3, uint32_t b0, uint32_t b1) {
    asm volatile("mma.sync.aligned.m16n8k16.row.col.f32.bf16.bf16.f32 "
                 "{%0,%1,%2,%3}, {%4,%5,%6,%7}, {%8,%9}, {%0,%1,%2,%3};"
                 : "+f"(d[0]), "+f"(d[1]), "+f"(d[2]), "+f"(d[3])
                 : "r"(a0), "r"(a1), "r"(a2), "r"(a3), "r"(b0), "r"(b1));
}

// ============================ repack (tiny, once per launch) ============================
__global__ void repack_kernel(const float* __restrict__ W_att1,
                              const float* __restrict__ W_node,
                              const float* __restrict__ W_neib) {
    int t = threadIdx.x;  // 1024 threads
    if (t < 1024) {       // g_W1q: [q][h] = d-quad packed f32x2 (exact)
        int q = t >> 5, h = t & 31;
        ulonglong2 w;
        w.x = pack2(W_att1[(4 * q) * H + h],     W_att1[(4 * q + 1) * H + h]);
        w.y = pack2(W_att1[(4 * q + 2) * H + h], W_att1[(4 * q + 3) * H + h]);
        g_W1q[t] = w;
    }
    // W1^T padded bf16 hi/lo images: row = h (32), col = d (128), stride 272B
    {
        char* bhi = reinterpret_cast<char*>(g_BThi4);
        char* blo = reinterpret_cast<char*>(g_BTlo4);
        for (int i = t; i < 128 * 32; i += 1024) {
            int d = i >> 5, h = i & 31;
            float w = W_att1[d * H + h];
            __nv_bfloat16 hi = __float2bfloat16_rn(w);
            __nv_bfloat16 lo = __float2bfloat16_rn(w - __bfloat162float(hi));
            *reinterpret_cast<__nv_bfloat16*>(bhi + h * ASTRIDE + d * 2) = hi;
            *reinterpret_cast<__nv_bfloat16*>(blo + h * ASTRIDE + d * 2) = lo;
        }
    }
    for (int i = t; i < 32 * 128; i += 1024) {
        int q = i >> 7, col = i & 127;
        g_Wn4[i] = make_float4(W_node[(4 * q) * O + col],     W_node[(4 * q + 1) * O + col],
                               W_node[(4 * q + 2) * O + col], W_node[(4 * q + 3) * O + col]);
        g_Wb4[i] = make_float4(W_neib[(4 * q) * O + col],     W_neib[(4 * q + 1) * O + col],
                               W_neib[(4 * q + 2) * O + col], W_neib[(4 * q + 3) * O + col]);
    }
}

// ============================ epilogue branch helper ============================
__device__ __forceinline__ void epilogue_branch(const float4* __restrict__ src,   // [4][32]
                                                const float4* __restrict__ W4,
                                                float* __restrict__ out,
                                                int colbase, int col, int base, int n) {
    u64 acc01 = 0ull, acc23 = 0ull;
    #pragma unroll 4
    for (int q = 0; q < 32; ++q) {
        float4 wv = W4[q * 128 + col];
        float4 s0 = src[q], s1 = src[32 + q], s2 = src[64 + q], s3 = src[96 + q];
        #pragma unroll
        for (int i = 0; i < 4; ++i) {
            float wf = fc(wv, i);
            u64 w2 = pack2(wf, wf);
            acc01 = ffma2(pack2(fc(s0, i), fc(s1, i)), w2, acc01);
            acc23 = ffma2(pack2(fc(s2, i), fc(s3, i)), w2, acc23);
        }
    }
    float2 f01 = unpack2(acc01), f23 = unpack2(acc23);
    int oc = colbase + col;
    if (base     < n) out[(size_t)(base)     * 256 + oc] = fmaxf(f01.x, 0.f);
    if (base + 1 < n) out[(size_t)(base + 1) * 256 + oc] = fmaxf(f01.y, 0.f);
    if (base + 2 < n) out[(size_t)(base + 2) * 256 + oc] = fmaxf(f23.x, 0.f);
    if (base + 3 < n) out[(size_t)(base + 3) * 256 + oc] = fmaxf(f23.y, 0.f);
}

// ============================ main fused kernel ============================
__global__ __launch_bounds__(NTHREADS, 2)
void attn_agg_mma_kernel(const float* __restrict__ node_feats,
                         const float* __restrict__ neib_feats,
                         const float* __restrict__ W_att2,
                         float* __restrict__ out, int n)
{
    extern __shared__ char dsm[];
    const uint32_t smem = smem_u32(dsm);

    const int tid  = threadIdx.x;
    const int lane = tid & 31;
    const int warp = tid >> 5;         // 0..3, one node each

    float*  sW2  = reinterpret_cast<float*>(dsm + OFF_W2);
    float4* sX4  = reinterpret_cast<float4*>(dsm + OFF_X);     // [4][32]
    float4* sAg4 = reinterpret_cast<float4*>(dsm + OFF_AGG);   // [4][32]
    float*  sU   = reinterpret_cast<float*>(dsm + OFF_U);
    float*  sT   = reinterpret_cast<float*>(dsm + OFF_T);

    const int base = blockIdx.x * G;
    const int node = min(base + warp, n - 1);

    // ---- phase 1: stage shared weights, node rows, and per-warp A tiles ----
    {
        float4* bs = reinterpret_cast<float4*>(dsm + OFF_BHI);
        for (int i = tid; i < 2 * (ATILE / 16); i += NTHREADS)
            bs[i] = (i < ATILE / 16) ? g_BThi4[i] : g_BTlo4[i - ATILE / 16];
        #pragma unroll
        for (int i = 0; i < 8; ++i) {
            int j = tid + i * NTHREADS;
            sW2[(j >> 5) * 33 + (j & 31)] = W_att2[j];
        }
        sX4[warp * 32 + lane] =
            reinterpret_cast<const float4*>(node_feats)[(size_t)node * 32 + lane];
    }
    {
        // convert this warp's 32 neighbor rows fp32 -> bf16 hi/lo into padded tiles
        const float4* src4 = reinterpret_cast<const float4*>(
                                 neib_feats + (size_t)node * (K * D));
        char* Ahi = dsm + OFF_AHI + warp * ATILE;
        char* Alo = dsm + OFF_ALO + warp * ATILE;
        #pragma unroll 4
        for (int k = 0; k < 32; ++k) {
            float4 v = src4[k * 32 + lane];
            __nv_bfloat162 h0 = __floats2bfloat162_rn(v.x, v.y);
            __nv_bfloat162 h1 = __floats2bfloat162_rn(v.z, v.w);
            float2 f0 = __bfloat1622float2(h0);
            float2 f1 = __bfloat1622float2(h1);
            __nv_bfloat162 l0 = __floats2bfloat162_rn(v.x - f0.x, v.y - f0.y);
            __nv_bfloat162 l1 = __floats2bfloat162_rn(v.z - f1.x, v.w - f1.y);
            uint2 hv = make_uint2(*reinterpret_cast<uint32_t*>(&h0),
                                  *reinterpret_cast<uint32_t*>(&h1));
            uint2 lv = make_uint2(*reinterpret_cast<uint32_t*>(&l0),
                                  *reinterpret_cast<uint32_t*>(&l1));
            *reinterpret_cast<uint2*>(Ahi + k * ASTRIDE + lane * 8) = hv;
            *reinterpret_cast<uint2*>(Alo + k * ASTRIDE + lane * 8) = lv;
        }
    }
    __syncthreads();   // B tiles + W2 visible to all

    // ---- phase 2 (warp-local): u vector in exact fp32 ----
    {
        const float4* xv4 = sX4 + warp * 32;
        u64 a = 0ull;
        #pragma unroll
        for (int q = 0; q < 32; ++q) {
            ulonglong2 w = g_W1q[q * 32 + lane];
            float4 xv = xv4[q];
            a = ffma2(pack2(xv.x, xv.y), w.x, a);
            a = ffma2(pack2(xv.z, xv.w), w.y, a);
        }
        float2 qa = unpack2(a);
        sT[warp * 32 + lane] = tanhf(qa.x + qa.y);
        __syncwarp();
        float na = 0.f;
        #pragma unroll
        for (int h = 0; h < 32; ++h) na += sT[warp * 32 + h] * sW2[h * 33 + lane];
        __syncwarp();
        sT[warp * 32 + lane] = na;
        __syncwarp();
        float u = 0.f;
        #pragma unroll
        for (int h = 0; h < 32; ++h) u += sW2[lane * 33 + h] * sT[warp * 32 + h];
        sU[warp * 32 + lane] = u;
        __syncwarp();
    }

    // ---- phase 3 (warp-local): 32x32x128 MMA, split-bf16 3-pass ----
    float acc[2][4][4];
    #pragma unroll
    for (int m = 0; m < 2; ++m)
        #pragma unroll
        for (int nt = 0; nt < 4; ++nt)
            #pragma unroll
            for (int r = 0; r < 4; ++r) acc[m][nt][r] = 0.f;

    {
        const uint32_t AhiU = smem + OFF_AHI + warp * ATILE;
        const uint32_t AloU = smem + OFF_ALO + warp * ATILE;
        const uint32_t BhiU = smem + OFF_BHI;
        const uint32_t BloU = smem + OFF_BLO;
        const int lr = lane & 7, seg = lane >> 3;
        const uint32_t aOff = (uint32_t)(((seg & 1) * 8 + lr) * ASTRIDE + (seg >> 1) * 16);
        const uint32_t bOff = (uint32_t)(((seg >> 1) * 8 + lr) * ASTRIDE + (seg & 1) * 16);

        #pragma unroll
        for (int s = 0; s < 8; ++s) {
            const uint32_t dby = s * 32;   // k-step = 16 bf16 = 32 bytes
            uint32_t aH[2][4], aL[2][4], bH[2][4], bL[2][4];
            ldsm4(aH[0][0], aH[0][1], aH[0][2], aH[0][3], AhiU + aOff + dby);
            ldsm4(aH[1][0], aH[1][1], aH[1][2], aH[1][3], AhiU + aOff + 16 * ASTRIDE + dby);
            ldsm4(bH[0][0], bH[0][1], bH[0][2], bH[0][3], BhiU + bOff + dby);
            ldsm4(bH[1][0], bH[1][1], bH[1][2], bH[1][3], BhiU + bOff + 16 * ASTRIDE + dby);
            ldsm4(bL[0][0], bL[0][1], bL[0][2], bL[0][3], BloU + bOff + dby);
            ldsm4(bL[1][0], bL[1][1], bL[1][2], bL[1][3], BloU + bOff + 16 * ASTRIDE + dby);
            ldsm4(aL[0][0], aL[0][1], aL[0][2], aL[0][3], AloU + aOff + dby);
            ldsm4(aL[1][0], aL[1][1], aL[1][2], aL[1][3], AloU + aOff + 16 * ASTRIDE + dby);
            #pragma unroll
            for (int m = 0; m < 2; ++m) {
                #pragma unroll
                for (int nt = 0; nt < 4; ++nt) {
                    uint32_t bh0 = bH[nt >> 1][(nt & 1) * 2], bh1 = bH[nt >> 1][(nt & 1) * 2 + 1];
                    uint32_t bl0 = bL[nt >> 1][(nt & 1) * 2], bl1 = bL[nt >> 1][(nt & 1) * 2 + 1];
                    mma16816(acc[m][nt], aH[m][0], aH[m][1], aH[m][2], aH[m][3], bh0, bh1);
                    mma16816(acc[m][nt], aH[m][0], aH[m][1], aH[m][2], aH[m][3], bl0, bl1);
                    mma16816(acc[m][nt], aL[m][0], aL[m][1], aL[m][2], aL[m][3], bh0, bh1);
                }
            }
        }
    }

    // ---- phase 4 (warp-local): scores + softmax in registers ----
    // acc[m][nt] regs: {row g, col c0}, {row g, c0+1}, {row g+8, c0}, {row g+8, c0+1}
    // where g = lane/4, c0 = nt*8 + (lane%4)*2; m adds 16 to rows.
    float w4[4];
    {
        const float* sUf = sU + warp * 32;
        const int c0 = (lane & 3) * 2;
        float uu[8];
        #pragma unroll
        for (int nt = 0; nt < 4; ++nt) {
            uu[2 * nt]     = sUf[nt * 8 + c0];
            uu[2 * nt + 1] = sUf[nt * 8 + c0 + 1];
        }
        float p[4];   // rows g, g+8, g+16, g+24
        #pragma unroll
        for (int j = 0; j < 4; ++j) {
            int m = j >> 1, r0 = (j & 1) * 2;
            float s = 0.f;
            #pragma unroll
            for (int nt = 0; nt < 4; ++nt)
                s += ftanh(acc[m][nt][r0]) * uu[2 * nt]
                   + ftanh(acc[m][nt][r0 + 1]) * uu[2 * nt + 1];
            p[j] = s;
        }
        #pragma unroll
        for (int j = 0; j < 4; ++j) {
            p[j] += __shfl_xor_sync(0xffffffffu, p[j], 1);
            p[j] += __shfl_xor_sync(0xffffffffu, p[j], 2);
        }
        float mx = fmaxf(fmaxf(p[0], p[1]), fmaxf(p[2], p[3]));
        #pragma unroll
        for (int o = 4; o <= 16; o <<= 1) mx = fmaxf(mx, __shfl_xor_sync(0xffffffffu, mx, o));
        float S = 0.f;
        #pragma unroll
        for (int j = 0; j < 4; ++j) { w4[j] = __expf(p[j] - mx); S += w4[j]; }
        #pragma unroll
        for (int o = 4; o <= 16; o <<= 1) S += __shfl_xor_sync(0xffffffffu, S, o);
        float iZ = __fdividef(1.0f, S);
        #pragma unroll
        for (int j = 0; j < 4; ++j) w4[j] *= iZ;
    }

    // ---- phase 5 (warp-local): weighted aggregation (rows = hi + lo) ----
    {
        const char* Ahi = dsm + OFF_AHI + warp * ATILE;
        const char* Alo = dsm + OFF_ALO + warp * ATILE;
        float4 ag = make_float4(0.f, 0.f, 0.f, 0.f);
        #pragma unroll
        for (int k = 0; k < 32; ++k) {
            // row k's weight lives in lanes with g == k%8, slot k/8; lane (k%8)*4 is one of them
            float wk = __shfl_sync(0xffffffffu, w4[k >> 3], (k & 7) * 4);
            uint2 hv = *reinterpret_cast<const uint2*>(Ahi + k * ASTRIDE + lane * 8);
            uint2 lv = *reinterpret_cast<const uint2*>(Alo + k * ASTRIDE + lane * 8);
            float2 a0 = __bfloat1622float2(*reinterpret_cast<__nv_bfloat162*>(&hv.x));
            float2 a1 = __bfloat1622float2(*reinterpret_cast<__nv_bfloat162*>(&hv.y));
            float2 c0 = __bfloat1622float2(*reinterpret_cast<__nv_bfloat162*>(&lv.x));
            float2 c1 = __bfloat1622float2(*reinterpret_cast<__nv_bfloat162*>(&lv.y));
            ag.x += wk * (a0.x + c0.x);
            ag.y += wk * (a0.y + c0.y);
            ag.z += wk * (a1.x + c1.x);
            ag.w += wk * (a1.y + c1.y);
        }
        sAg4[warp * 32 + lane] = ag;   // d-quad 'lane' of node 'warp'
    }
    __syncthreads();

    // ---- phase 6: block-cooperative epilogue (col = tid, 4 nodes each) ----
    epilogue_branch(sX4,  g_Wn4, out, 0, tid, base, n);
    epilogue_branch(sAg4, g_Wb4, out, O, tid, base, n);
}

extern "C" void kernel_launch(void* const* d_in, const int* in_sizes, int n_in,
                              void* d_out, int out_size) {
    const float* node_feats = (const float*)d_in[0];
    const float* neib_feats = (const float*)d_in[1];
    // d_in[2] = node_ids, d_in[3] = neib_ids : unused by the reference computation
    const float* W_att1 = (const float*)d_in[4];
    const float* W_att2 = (const float*)d_in[5];
    const float* W_node = (const float*)d_in[6];
    const float* W_neib = (const float*)d_in[7];

    cudaFuncSetAttribute(attn_agg_mma_kernel,
                         cudaFuncAttributeMaxDynamicSharedMemorySize, SMEM_BYTES);

    int n = in_sizes[0] / D;
    repack_kernel<<<1, 1024>>>(W_att1, W_node, W_neib);
    int blocks = (n + G - 1) / G;
    attn_agg_mma_kernel<<<blocks, NTHREADS, SMEM_BYTES>>>(node_feats, neib_feats,
                                                          W_att2, (float*)d_out, n);
}

// round 11
// speedup vs baseline: 1.8350x; 1.8350x over previous
#include <cuda_runtime.h>
#include <cuda_bf16.h>
#include <cstdint>

typedef unsigned long long u64;

constexpr int D = 128;
constexpr int K = 32;
constexpr int H = 32;
constexpr int O = 128;
constexpr int G = 4;                 // nodes per CTA (2 warps per node)
constexpr int NTHREADS = 256;

constexpr int ASTRIDE = 272;         // bytes per A-tile row (128 bf16 + 8 pad)
constexpr int ATILE   = 32 * ASTRIDE;  // 8704 B per 32x128 bf16 tile

// ---- dynamic smem layout (bytes, 16B aligned) ----
constexpr uint32_t OFF_AHI = 0;           // 4 nodes x 8704
constexpr uint32_t OFF_ALO = 34816;       // 4 x 8704
constexpr uint32_t OFF_W2  = 69632;       // 32*33*4 = 4224
constexpr uint32_t OFF_X   = 73856;       // 4*32 float4 = 2048
constexpr uint32_t OFF_AGP = 75904;       // 4 nodes x 2 halves x 32 float4 = 4096
constexpr uint32_t OFF_U   = 80000;       // 8 warps x 32 float = 1024
constexpr uint32_t OFF_T   = 81024;       // 1024
constexpr uint32_t OFF_SC  = 82048;       // 4 nodes x 32 float = 512
constexpr uint32_t SMEM_BYTES = 82560;

// ---- persistent repacked weights ----
__device__ ulonglong2 g_W1q[32 * 32];     // fp32-packed W1 (exact u path)
// W1^T bf16 hi/lo as MMA B-fragments: [(s*2+p)*32 + lane] = uint4
//   .x,.y = frag (b0,b1) for n-tile 2p ; .z,.w = frag for n-tile 2p+1
__device__ uint4      g_BfHi[8 * 2 * 32];
__device__ uint4      g_BfLo[8 * 2 * 32];
__device__ float4     g_Wn4[32 * 128];    // [q][col] = W_node[4q..4q+3][col]
__device__ float4     g_Wb4[32 * 128];

// ---- helpers ----
__device__ __forceinline__ u64 pack2(float lo, float hi) {
    u64 r; asm("mov.b64 %0, {%1, %2};" : "=l"(r) : "f"(lo), "f"(hi)); return r;
}
__device__ __forceinline__ float2 unpack2(u64 v) {
    float2 f; asm("mov.b64 {%0, %1}, %2;" : "=f"(f.x), "=f"(f.y) : "l"(v)); return f;
}
__device__ __forceinline__ u64 ffma2(u64 a, u64 b, u64 c) {
    u64 d; asm("fma.rn.f32x2 %0, %1, %2, %3;" : "=l"(d) : "l"(a), "l"(b), "l"(c)); return d;
}
__device__ __forceinline__ float fc(const float4& v, int i) {
    return i == 0 ? v.x : (i == 1 ? v.y : (i == 2 ? v.z : v.w));
}
__device__ __forceinline__ uint32_t smem_u32(const void* p) {
    uint32_t a;
    asm("{ .reg .u64 t; cvta.to.shared.u64 t, %1; cvt.u32.u64 %0, t; }" : "=r"(a) : "l"(p));
    return a;
}
__device__ __forceinline__ float ftanh(float x) {
    float e = __expf(2.0f * x);
    return 1.0f - __fdividef(2.0f, e + 1.0f);
}
__device__ __forceinline__ void ldsm4(uint32_t& r0, uint32_t& r1, uint32_t& r2, uint32_t& r3,
                                      uint32_t addr) {
    asm volatile("ldmatrix.sync.aligned.m8n8.x4.shared.b16 {%0,%1,%2,%3}, [%4];"
                 : "=r"(r0), "=r"(r1), "=r"(r2), "=r"(r3) : "r"(addr));
}
__device__ __forceinline__ void mma16816(float* d, uint32_t a0, uint32_t a1, uint32_t a2,
                                         uint32_t a3, uint32_t b0, uint32_t b1) {
    asm volatile("mma.sync.aligned.m16n8k16.row.col.f32.bf16.bf16.f32 "
                 "{%0,%1,%2,%3}, {%4,%5,%6,%7}, {%8,%9}, {%0,%1,%2,%3};"
                 : "+f"(d[0]), "+f"(d[1]), "+f"(d[2]), "+f"(d[3])
                 : "r"(a0), "r"(a1), "r"(a2), "r"(a3), "r"(b0), "r"(b1));
}

// ============================ repack (tiny, once per launch) ============================
__device__ __forceinline__ uint32_t pkbf(float a, float b) {
    __nv_bfloat162 t = __floats2bfloat162_rn(a, b);
    return *reinterpret_cast<uint32_t*>(&t);
}

__global__ void repack_kernel(const float* __restrict__ W_att1,
                              const float* __restrict__ W_node,
                              const float* __restrict__ W_neib) {
    int t = threadIdx.x;  // 1024 threads
    if (t < 1024) {       // g_W1q: [q][h] = d-quad packed f32x2 (exact)
        int q = t >> 5, h = t & 31;
        ulonglong2 w;
        w.x = pack2(W_att1[(4 * q) * H + h],     W_att1[(4 * q + 1) * H + h]);
        w.y = pack2(W_att1[(4 * q + 2) * H + h], W_att1[(4 * q + 3) * H + h]);
        g_W1q[t] = w;
    }
    if (t < 512) {        // B fragments (hi + lo)
        int s = t >> 6, p = (t >> 5) & 1, ln = t & 31;
        int k0 = s * 16 + (ln & 3) * 2;
        int hA = (2 * p) * 8 + (ln >> 2);
        int hB = (2 * p + 1) * 8 + (ln >> 2);
        float w[4][2];    // [k-slot][h-col]
        float wh[4][2], wl[4][2];
        int ks[4] = {k0, k0 + 1, k0 + 8, k0 + 9};
        #pragma unroll
        for (int i = 0; i < 4; ++i) {
            w[i][0] = W_att1[ks[i] * H + hA];
            w[i][1] = W_att1[ks[i] * H + hB];
            #pragma unroll
            for (int j = 0; j < 2; ++j) {
                float hf = __bfloat162float(__float2bfloat16_rn(w[i][j]));
                wh[i][j] = w[i][j];
                wl[i][j] = w[i][j] - hf;
            }
        }
        uint4 hi, lo;
        hi.x = pkbf(wh[0][0], wh[1][0]);  hi.y = pkbf(wh[2][0], wh[3][0]);
        hi.z = pkbf(wh[0][1], wh[1][1]);  hi.w = pkbf(wh[2][1], wh[3][1]);
        lo.x = pkbf(wl[0][0], wl[1][0]);  lo.y = pkbf(wl[2][0], wl[3][0]);
        lo.z = pkbf(wl[0][1], wl[1][1]);  lo.w = pkbf(wl[2][1], wl[3][1]);
        g_BfHi[t] = hi;
        g_BfLo[t] = lo;
    }
    for (int i = t; i < 32 * 128; i += 1024) {
        int q = i >> 7, col = i & 127;
        g_Wn4[i] = make_float4(W_node[(4 * q) * O + col],     W_node[(4 * q + 1) * O + col],
                               W_node[(4 * q + 2) * O + col], W_node[(4 * q + 3) * O + col]);
        g_Wb4[i] = make_float4(W_neib[(4 * q) * O + col],     W_neib[(4 * q + 1) * O + col],
                               W_neib[(4 * q + 2) * O + col], W_neib[(4 * q + 3) * O + col]);
    }
}

// ============================ epilogue helper ============================
__device__ __forceinline__ void epilogue_branch(const float4* __restrict__ src, int stride,
                                                const float4* __restrict__ W4,
                                                float* __restrict__ out,
                                                int colbase, int col, int base, int n) {
    u64 acc01 = 0ull, acc23 = 0ull;
    #pragma unroll 4
    for (int q = 0; q < 32; ++q) {
        float4 wv = W4[q * 128 + col];
        float4 s0 = src[q], s1 = src[stride + q], s2 = src[2 * stride + q], s3 = src[3 * stride + q];
        #pragma unroll
        for (int i = 0; i < 4; ++i) {
            float wf = fc(wv, i);
            u64 w2 = pack2(wf, wf);
            acc01 = ffma2(pack2(fc(s0, i), fc(s1, i)), w2, acc01);
            acc23 = ffma2(pack2(fc(s2, i), fc(s3, i)), w2, acc23);
        }
    }
    float2 f01 = unpack2(acc01), f23 = unpack2(acc23);
    int oc = colbase + col;
    if (base     < n) out[(size_t)(base)     * 256 + oc] = fmaxf(f01.x, 0.f);
    if (base + 1 < n) out[(size_t)(base + 1) * 256 + oc] = fmaxf(f01.y, 0.f);
    if (base + 2 < n) out[(size_t)(base + 2) * 256 + oc] = fmaxf(f23.x, 0.f);
    if (base + 3 < n) out[(size_t)(base + 3) * 256 + oc] = fmaxf(f23.y, 0.f);
}

// ============================ main fused kernel ============================
__global__ __launch_bounds__(NTHREADS, 2)
void attn_agg_mma_kernel(const float* __restrict__ node_feats,
                         const float* __restrict__ neib_feats,
                         const float* __restrict__ W_att2,
                         float* __restrict__ out, int n)
{
    extern __shared__ char dsm[];
    const uint32_t smem = smem_u32(dsm);

    const int tid  = threadIdx.x;
    const int lane = tid & 31;
    const int warp = tid >> 5;         // 0..7
    const int g    = warp >> 1;        // node within CTA (0..3)
    const int hh   = warp & 1;         // row-half (0: rows 0-15, 1: rows 16-31)

    float*  sW2  = reinterpret_cast<float*>(dsm + OFF_W2);
    float4* sX4  = reinterpret_cast<float4*>(dsm + OFF_X);     // [4][32]
    float4* sAgP = reinterpret_cast<float4*>(dsm + OFF_AGP);   // [4][2][32]
    float*  sU   = reinterpret_cast<float*>(dsm + OFF_U);      // per-warp [32]
    float*  sT   = reinterpret_cast<float*>(dsm + OFF_T);      // per-warp [32]
    float*  sSc  = reinterpret_cast<float*>(dsm + OFF_SC);     // [4][32]

    const int base = blockIdx.x * G;
    const int node = min(base + g, n - 1);

    // ---- phase 1: stage W2, node row (hh==0), and this warp's 16 A rows ----
    #pragma unroll
    for (int i = 0; i < 4; ++i) {
        int j = tid + i * NTHREADS;
        sW2[(j >> 5) * 33 + (j & 31)] = W_att2[j];
    }
    if (hh == 0)
        sX4[g * 32 + lane] =
            reinterpret_cast<const float4*>(node_feats)[(size_t)node * 32 + lane];
    {
        const float4* src4 = reinterpret_cast<const float4*>(
                                 neib_feats + (size_t)node * (K * D));
        char* Ahi = dsm + OFF_AHI + g * ATILE;
        char* Alo = dsm + OFF_ALO + g * ATILE;
        #pragma unroll 4
        for (int j = 0; j < 16; ++j) {
            int k = hh * 16 + j;
            float4 v = src4[k * 32 + lane];
            __nv_bfloat162 h0 = __floats2bfloat162_rn(v.x, v.y);
            __nv_bfloat162 h1 = __floats2bfloat162_rn(v.z, v.w);
            float2 f0 = __bfloat1622float2(h0);
            float2 f1 = __bfloat1622float2(h1);
            __nv_bfloat162 l0 = __floats2bfloat162_rn(v.x - f0.x, v.y - f0.y);
            __nv_bfloat162 l1 = __floats2bfloat162_rn(v.z - f1.x, v.w - f1.y);
            uint2 hv = make_uint2(*reinterpret_cast<uint32_t*>(&h0),
                                  *reinterpret_cast<uint32_t*>(&h1));
            uint2 lv = make_uint2(*reinterpret_cast<uint32_t*>(&l0),
                                  *reinterpret_cast<uint32_t*>(&l1));
            *reinterpret_cast<uint2*>(Ahi + k * ASTRIDE + lane * 8) = hv;
            *reinterpret_cast<uint2*>(Alo + k * ASTRIDE + lane * 8) = lv;
        }
    }
    __syncthreads();

    // ---- phase 2: u vector, exact fp32 (both warps of a pair redundantly) ----
    float* sTw = sT + warp * 32;
    float* sUw = sU + warp * 32;
    {
        const float4* xv4 = sX4 + g * 32;
        u64 a = 0ull;
        #pragma unroll
        for (int q = 0; q < 32; ++q) {
            ulonglong2 w = g_W1q[q * 32 + lane];
            float4 xv = xv4[q];
            a = ffma2(pack2(xv.x, xv.y), w.x, a);
            a = ffma2(pack2(xv.z, xv.w), w.y, a);
        }
        float2 qa = unpack2(a);
        sTw[lane] = tanhf(qa.x + qa.y);
        __syncwarp();
        float na = 0.f;
        #pragma unroll
        for (int h = 0; h < 32; ++h) na += sTw[h] * sW2[h * 33 + lane];
        __syncwarp();
        sTw[lane] = na;
        __syncwarp();
        float u = 0.f;
        #pragma unroll
        for (int h = 0; h < 32; ++h) u += sW2[lane * 33 + h] * sTw[h];
        sUw[lane] = u;
        __syncwarp();
    }

    // ---- phase 3: m16n32k128 MMA on this warp's 16 rows (split-bf16, 3 terms) ----
    float acc[4][4];
    #pragma unroll
    for (int nt = 0; nt < 4; ++nt)
        #pragma unroll
        for (int r = 0; r < 4; ++r) acc[nt][r] = 0.f;
    {
        const uint32_t AhiU = smem + OFF_AHI + g * ATILE + hh * 16 * ASTRIDE;
        const uint32_t AloU = smem + OFF_ALO + g * ATILE + hh * 16 * ASTRIDE;
        const int lr = lane & 7, seg = lane >> 3;
        const uint32_t aOff = (uint32_t)(((seg & 1) * 8 + lr) * ASTRIDE + (seg >> 1) * 16);

        #pragma unroll
        for (int s = 0; s < 8; ++s) {
            const uint32_t dby = s * 32;
            uint32_t aH[4], aL[4];
            ldsm4(aH[0], aH[1], aH[2], aH[3], AhiU + aOff + dby);
            ldsm4(aL[0], aL[1], aL[2], aL[3], AloU + aOff + dby);
            uint4 bh0 = g_BfHi[(s * 2)     * 32 + lane];
            uint4 bh1 = g_BfHi[(s * 2 + 1) * 32 + lane];
            uint4 bl0 = g_BfLo[(s * 2)     * 32 + lane];
            uint4 bl1 = g_BfLo[(s * 2 + 1) * 32 + lane];
            mma16816(acc[0], aH[0], aH[1], aH[2], aH[3], bh0.x, bh0.y);
            mma16816(acc[0], aH[0], aH[1], aH[2], aH[3], bl0.x, bl0.y);
            mma16816(acc[0], aL[0], aL[1], aL[2], aL[3], bh0.x, bh0.y);
            mma16816(acc[1], aH[0], aH[1], aH[2], aH[3], bh0.z, bh0.w);
            mma16816(acc[1], aH[0], aH[1], aH[2], aH[3], bl0.z, bl0.w);
            mma16816(acc[1], aL[0], aL[1], aL[2], aL[3], bh0.z, bh0.w);
            mma16816(acc[2], aH[0], aH[1], aH[2], aH[3], bh1.x, bh1.y);
            mma16816(acc[2], aH[0], aH[1], aH[2], aH[3], bl1.x, bl1.y);
            mma16816(acc[2], aL[0], aL[1], aL[2], aL[3], bh1.x, bh1.y);
            mma16816(acc[3], aH[0], aH[1], aH[2], aH[3], bh1.z, bh1.w);
            mma16816(acc[3], aH[0], aH[1], aH[2], aH[3], bl1.z, bl1.w);
            mma16816(acc[3], aL[0], aL[1], aL[2], aL[3], bh1.z, bh1.w);
        }
    }

    // ---- phase 4: scores for this warp's 16 rows ----
    // acc[nt] regs: {row r=lane/4, col c0,c0+1}, {row r+8, col c0,c0+1}, c0 = nt*8+(lane%4)*2
    {
        const int c0 = (lane & 3) * 2;
        float uu[8];
        #pragma unroll
        for (int nt = 0; nt < 4; ++nt) {
            uu[2 * nt]     = sUw[nt * 8 + c0];
            uu[2 * nt + 1] = sUw[nt * 8 + c0 + 1];
        }
        float p0 = 0.f, p1 = 0.f;
        #pragma unroll
        for (int nt = 0; nt < 4; ++nt) {
            p0 += ftanh(acc[nt][0]) * uu[2 * nt] + ftanh(acc[nt][1]) * uu[2 * nt + 1];
            p1 += ftanh(acc[nt][2]) * uu[2 * nt] + ftanh(acc[nt][3]) * uu[2 * nt + 1];
        }
        p0 += __shfl_xor_sync(0xffffffffu, p0, 1);
        p0 += __shfl_xor_sync(0xffffffffu, p0, 2);
        p1 += __shfl_xor_sync(0xffffffffu, p1, 1);
        p1 += __shfl_xor_sync(0xffffffffu, p1, 2);
        if ((lane & 3) == 0) {
            int r = lane >> 2;
            sSc[g * 32 + hh * 16 + r]     = p0;
            sSc[g * 32 + hh * 16 + 8 + r] = p1;
        }
    }
    __syncthreads();

    // ---- phase 5: softmax (redundant per pair) + aggregate own 16 rows ----
    {
        float sv = sSc[g * 32 + lane];
        float mx = sv;
        #pragma unroll
        for (int o = 16; o > 0; o >>= 1) mx = fmaxf(mx, __shfl_xor_sync(0xffffffffu, mx, o));
        float e = __expf(sv - mx);
        float Z = e;
        #pragma unroll
        for (int o = 16; o > 0; o >>= 1) Z += __shfl_xor_sync(0xffffffffu, Z, o);
        float wv = e * __fdividef(1.0f, Z);

        const char* Ahi = dsm + OFF_AHI + g * ATILE;
        const char* Alo = dsm + OFF_ALO + g * ATILE;
        float4 ag = make_float4(0.f, 0.f, 0.f, 0.f);
        #pragma unroll
        for (int j = 0; j < 16; ++j) {
            int row = hh * 16 + j;
            float wk = __shfl_sync(0xffffffffu, wv, row);
            uint2 hv = *reinterpret_cast<const uint2*>(Ahi + row * ASTRIDE + lane * 8);
            uint2 lv = *reinterpret_cast<const uint2*>(Alo + row * ASTRIDE + lane * 8);
            float2 a0 = __bfloat1622float2(*reinterpret_cast<__nv_bfloat162*>(&hv.x));
            float2 a1 = __bfloat1622float2(*reinterpret_cast<__nv_bfloat162*>(&hv.y));
            float2 c0 = __bfloat1622float2(*reinterpret_cast<__nv_bfloat162*>(&lv.x));
            float2 c1 = __bfloat1622float2(*reinterpret_cast<__nv_bfloat162*>(&lv.y));
            ag.x += wk * (a0.x + c0.x);
            ag.y += wk * (a0.y + c0.y);
            ag.z += wk * (a1.x + c1.x);
            ag.w += wk * (a1.y + c1.y);
        }
        sAgP[(g * 2 + hh) * 32 + lane] = ag;
    }
    __syncthreads();

    // ---- phase 6a: sum the two agg halves (threads 128-255, one entry each) ----
    if (tid >= 128) {
        int i = tid - 128;                 // 0..127 = (node g2)*32 + q
        int g2 = i >> 5, q = i & 31;
        float4 a = sAgP[g2 * 64 + q];
        float4 b = sAgP[g2 * 64 + 32 + q];
        sAgP[g2 * 64 + q] = make_float4(a.x + b.x, a.y + b.y, a.z + b.z, a.w + b.w);
    }
    __syncthreads();

    // ---- phase 6b: block-cooperative epilogue (each thread: one branch, one col) ----
    if (tid < 128)
        epilogue_branch(sX4, 32, g_Wn4, out, 0, tid, base, n);
    else
        epilogue_branch(sAgP, 64, g_Wb4, out, O, tid - 128, base, n);
}

extern "C" void kernel_launch(void* const* d_in, const int* in_sizes, int n_in,
                              void* d_out, int out_size) {
    const float* node_feats = (const float*)d_in[0];
    const float* neib_feats = (const float*)d_in[1];
    // d_in[2] = node_ids, d_in[3] = neib_ids : unused by the reference computation
    const float* W_att1 = (const float*)d_in[4];
    const float* W_att2 = (const float*)d_in[5];
    const float* W_node = (const float*)d_in[6];
    const float* W_neib = (const float*)d_in[7];

    cudaFuncSetAttribute(attn_agg_mma_kernel,
                         cudaFuncAttributeMaxDynamicSharedMemorySize, SMEM_BYTES);

    int n = in_sizes[0] / D;
    repack_kernel<<<1, 1024>>>(W_att1, W_node, W_neib);
    int blocks = (n + G - 1) / G;
    attn_agg_mma_kernel<<<blocks, NTHREADS, SMEM_BYTES>>>(node_feats, neib_feats,
                                                          W_att2, (float*)d_out, n);
}

// round 13
// speedup vs baseline: 1.9533x; 1.0644x over previous
#include <cuda_runtime.h>
#include <cuda_bf16.h>
#include <cstdint>

typedef unsigned long long u64;

constexpr int D = 128;
constexpr int K = 32;
constexpr int H = 32;
constexpr int O = 128;
constexpr int G = 4;                 // nodes per CTA
constexpr int NTHREADS = 256;

constexpr int ASTRIDE = 272;         // bytes per A-tile row (128 bf16 + 8 pad)
constexpr int ATILE   = 32 * ASTRIDE;  // 8704 B per 32x128 bf16 tile

// ---- dynamic smem layout (bytes, 16B aligned) ----
constexpr uint32_t OFF_AHI = 0;           // 4 nodes x 8704
constexpr uint32_t OFF_ALO = 34816;       // 4 x 8704
constexpr uint32_t OFF_W2  = 69632;       // 32*33*4 = 4224
constexpr uint32_t OFF_X   = 73856;       // 4*32 float4 = 2048
constexpr uint32_t OFF_AG  = 75904;       // 4*32 float4 = 2048
constexpr uint32_t OFF_U   = 77952;       // 4 nodes x 32 float = 512
constexpr uint32_t OFF_T   = 78464;       // 4 nodes x 32 float = 512
constexpr uint32_t SMEM_BYTES = 78976;

// ---- persistent repacked weights ----
__device__ ulonglong2 g_W1q[32 * 32];     // fp32-packed W1 (exact u path)
// W1^T bf16 hi/lo as MMA B-fragments: [(s*2+p)*32 + lane] = uint4
//   .x,.y = frag (b0,b1) for n-tile 2p ; .z,.w = frag for n-tile 2p+1
__device__ uint4      g_BfHi[8 * 2 * 32];
__device__ uint4      g_BfLo[8 * 2 * 32];
__device__ float4     g_Wn4[32 * 128];    // [q][col] = W_node[4q..4q+3][col]
__device__ float4     g_Wb4[32 * 128];

// ---- helpers ----
__device__ __forceinline__ u64 pack2(float lo, float hi) {
    u64 r; asm("mov.b64 %0, {%1, %2};" : "=l"(r) : "f"(lo), "f"(hi)); return r;
}
__device__ __forceinline__ float2 unpack2(u64 v) {
    float2 f; asm("mov.b64 {%0, %1}, %2;" : "=f"(f.x), "=f"(f.y) : "l"(v)); return f;
}
__device__ __forceinline__ u64 ffma2(u64 a, u64 b, u64 c) {
    u64 d; asm("fma.rn.f32x2 %0, %1, %2, %3;" : "=l"(d) : "l"(a), "l"(b), "l"(c)); return d;
}
__device__ __forceinline__ float fc(const float4& v, int i) {
    return i == 0 ? v.x : (i == 1 ? v.y : (i == 2 ? v.z : v.w));
}
__device__ __forceinline__ uint32_t smem_u32(const void* p) {
    uint32_t a;
    asm("{ .reg .u64 t; cvta.to.shared.u64 t, %1; cvt.u32.u64 %0, t; }" : "=r"(a) : "l"(p));
    return a;
}
__device__ __forceinline__ float ftanh(float x) {
    float e = __expf(2.0f * x);
    return 1.0f - __fdividef(2.0f, e + 1.0f);
}
__device__ __forceinline__ void ldsm4(uint32_t& r0, uint32_t& r1, uint32_t& r2, uint32_t& r3,
                                      uint32_t addr) {
    asm volatile("ldmatrix.sync.aligned.m8n8.x4.shared.b16 {%0,%1,%2,%3}, [%4];"
                 : "=r"(r0), "=r"(r1), "=r"(r2), "=r"(r3) : "r"(addr));
}
__device__ __forceinline__ void mma16816(float* d, uint32_t a0, uint32_t a1, uint32_t a2,
                                         uint32_t a3, uint32_t b0, uint32_t b1) {
    asm volatile("mma.sync.aligned.m16n8k16.row.col.f32.bf16.bf16.f32 "
                 "{%0,%1,%2,%3}, {%4,%5,%6,%7}, {%8,%9}, {%0,%1,%2,%3};"
                 : "+f"(d[0]), "+f"(d[1]), "+f"(d[2]), "+f"(d[3])
                 : "r"(a0), "r"(a1), "r"(a2), "r"(a3), "r"(b0), "r"(b1));
}
#define BAR_SYNC(id, cnt)   asm volatile("bar.sync %0, %1;"   :: "r"(id), "r"(cnt) : "memory")
#define BAR_ARRIVE(id, cnt) asm volatile("bar.arrive %0, %1;" :: "r"(id), "r"(cnt) : "memory")

// ============================ repack (tiny, once per launch) ============================
__device__ __forceinline__ uint32_t pkbf(float a, float b) {
    __nv_bfloat162 t = __floats2bfloat162_rn(a, b);
    return *reinterpret_cast<uint32_t*>(&t);
}

__global__ void repack_kernel(const float* __restrict__ W_att1,
                              const float* __restrict__ W_node,
                              const float* __restrict__ W_neib) {
    int t = threadIdx.x;  // 1024 threads
    if (t < 1024) {       // g_W1q: [q][h] = d-quad packed f32x2 (exact)
        int q = t >> 5, h = t & 31;
        ulonglong2 w;
        w.x = pack2(W_att1[(4 * q) * H + h],     W_att1[(4 * q + 1) * H + h]);
        w.y = pack2(W_att1[(4 * q + 2) * H + h], W_att1[(4 * q + 3) * H + h]);
        g_W1q[t] = w;
    }
    if (t < 512) {        // B fragments (hi + lo)
        int s = t >> 6, p = (t >> 5) & 1, ln = t & 31;
        int k0 = s * 16 + (ln & 3) * 2;
        int hA = (2 * p) * 8 + (ln >> 2);
        int hB = (2 * p + 1) * 8 + (ln >> 2);
        float wh[4][2], wl[4][2];
        int ks[4] = {k0, k0 + 1, k0 + 8, k0 + 9};
        #pragma unroll
        for (int i = 0; i < 4; ++i) {
            float wa = W_att1[ks[i] * H + hA];
            float wb = W_att1[ks[i] * H + hB];
            wh[i][0] = wa; wh[i][1] = wb;
            wl[i][0] = wa - __bfloat162float(__float2bfloat16_rn(wa));
            wl[i][1] = wb - __bfloat162float(__float2bfloat16_rn(wb));
        }
        uint4 hi, lo;
        hi.x = pkbf(wh[0][0], wh[1][0]);  hi.y = pkbf(wh[2][0], wh[3][0]);
        hi.z = pkbf(wh[0][1], wh[1][1]);  hi.w = pkbf(wh[2][1], wh[3][1]);
        lo.x = pkbf(wl[0][0], wl[1][0]);  lo.y = pkbf(wl[2][0], wl[3][0]);
        lo.z = pkbf(wl[0][1], wl[1][1]);  lo.w = pkbf(wl[2][1], wl[3][1]);
        g_BfHi[t] = hi;
        g_BfLo[t] = lo;
    }
    for (int i = t; i < 32 * 128; i += 1024) {
        int q = i >> 7, col = i & 127;
        g_Wn4[i] = make_float4(W_node[(4 * q) * O + col],     W_node[(4 * q + 1) * O + col],
                               W_node[(4 * q + 2) * O + col], W_node[(4 * q + 3) * O + col]);
        g_Wb4[i] = make_float4(W_neib[(4 * q) * O + col],     W_neib[(4 * q + 1) * O + col],
                               W_neib[(4 * q + 2) * O + col], W_neib[(4 * q + 3) * O + col]);
    }
}

// ============================ epilogue helper ============================
__device__ __forceinline__ void epilogue_branch(const float4* __restrict__ src,   // [4][32]
                                                const float4* __restrict__ W4,
                                                float* __restrict__ out,
                                                int colbase, int col, int base, int n) {
    u64 acc01 = 0ull, acc23 = 0ull;
    #pragma unroll 4
    for (int q = 0; q < 32; ++q) {
        float4 wv = W4[q * 128 + col];
        float4 s0 = src[q], s1 = src[32 + q], s2 = src[64 + q], s3 = src[96 + q];
        #pragma unroll
        for (int i = 0; i < 4; ++i) {
            float wf = fc(wv, i);
            u64 w2 = pack2(wf, wf);
            acc01 = ffma2(pack2(fc(s0, i), fc(s1, i)), w2, acc01);
            acc23 = ffma2(pack2(fc(s2, i), fc(s3, i)), w2, acc23);
        }
    }
    float2 f01 = unpack2(acc01), f23 = unpack2(acc23);
    int oc = colbase + col;
    if (base     < n) out[(size_t)(base)     * 256 + oc] = fmaxf(f01.x, 0.f);
    if (base + 1 < n) out[(size_t)(base + 1) * 256 + oc] = fmaxf(f01.y, 0.f);
    if (base + 2 < n) out[(size_t)(base + 2) * 256 + oc] = fmaxf(f23.x, 0.f);
    if (base + 3 < n) out[(size_t)(base + 3) * 256 + oc] = fmaxf(f23.y, 0.f);
}

// ============================ main fused kernel ============================
__global__ __launch_bounds__(NTHREADS, 2)
void attn_agg_mma_kernel(const float* __restrict__ node_feats,
                         const float* __restrict__ neib_feats,
                         const float* __restrict__ W_att2,
                         float* __restrict__ out, int n)
{
    extern __shared__ char dsm[];
    const uint32_t smem = smem_u32(dsm);

    const int tid  = threadIdx.x;
    const int lane = tid & 31;
    const int warp = tid >> 5;         // 0..7

    float*  sW2 = reinterpret_cast<float*>(dsm + OFF_W2);
    float4* sX4 = reinterpret_cast<float4*>(dsm + OFF_X);     // [4][32]
    float4* sAg = reinterpret_cast<float4*>(dsm + OFF_AG);    // [4][32]
    float*  sU  = reinterpret_cast<float*>(dsm + OFF_U);      // [4][32]
    float*  sT  = reinterpret_cast<float*>(dsm + OFF_T);      // [4][32]

    const int base = blockIdx.x * G;

    // ================= phase 1: staging (all 8 warps; pair per node) =================
    {
        const int sg = warp >> 1;       // node staged by this warp pair
        const int hh = warp & 1;        // row-half
        const int snode = min(base + sg, n - 1);
        #pragma unroll
        for (int i = 0; i < 4; ++i) {
            int j = tid + i * NTHREADS;
            sW2[(j >> 5) * 33 + (j & 31)] = W_att2[j];
        }
        if (hh == 0)
            sX4[sg * 32 + lane] =
                reinterpret_cast<const float4*>(node_feats)[(size_t)snode * 32 + lane];
        const float4* src4 = reinterpret_cast<const float4*>(
                                 neib_feats + (size_t)snode * (K * D));
        char* Ahi = dsm + OFF_AHI + sg * ATILE;
        char* Alo = dsm + OFF_ALO + sg * ATILE;
        #pragma unroll 4
        for (int j = 0; j < 16; ++j) {
            int k = hh * 16 + j;
            float4 v = src4[k * 32 + lane];
            __nv_bfloat162 h0 = __floats2bfloat162_rn(v.x, v.y);
            __nv_bfloat162 h1 = __floats2bfloat162_rn(v.z, v.w);
            float2 f0 = __bfloat1622float2(h0);
            float2 f1 = __bfloat1622float2(h1);
            __nv_bfloat162 l0 = __floats2bfloat162_rn(v.x - f0.x, v.y - f0.y);
            __nv_bfloat162 l1 = __floats2bfloat162_rn(v.z - f1.x, v.w - f1.y);
            uint2 hv = make_uint2(*reinterpret_cast<uint32_t*>(&h0),
                                  *reinterpret_cast<uint32_t*>(&h1));
            uint2 lv = make_uint2(*reinterpret_cast<uint32_t*>(&l0),
                                  *reinterpret_cast<uint32_t*>(&l1));
            *reinterpret_cast<uint2*>(Ahi + k * ASTRIDE + lane * 8) = hv;
            *reinterpret_cast<uint2*>(Alo + k * ASTRIDE + lane * 8) = lv;
        }
    }
    __syncthreads();

    if (warp >= 4) {
        // ================= helper warps: u (once per node) + x-branch epilogue =======
        const int g = warp - 4;
        float* sTg = sT + g * 32;
        {
            const float4* xv4 = sX4 + g * 32;
            u64 a = 0ull;
            #pragma unroll
            for (int q = 0; q < 32; ++q) {
                ulonglong2 w = g_W1q[q * 32 + lane];
                float4 xv = xv4[q];
                a = ffma2(pack2(xv.x, xv.y), w.x, a);
                a = ffma2(pack2(xv.z, xv.w), w.y, a);
            }
            float2 qa = unpack2(a);
            sTg[lane] = tanhf(qa.x + qa.y);
            __syncwarp();
            float na = 0.f;
            #pragma unroll
            for (int h = 0; h < 32; ++h) na += sTg[h] * sW2[h * 33 + lane];
            __syncwarp();
            sTg[lane] = na;
            __syncwarp();
            float u = 0.f;
            #pragma unroll
            for (int h = 0; h < 32; ++h) u += sW2[lane * 33 + h] * sTg[h];
            sU[g * 32 + lane] = u;
        }
        BAR_ARRIVE(g + 1, 64);          // signal u ready; don't block
        // x-branch epilogue runs concurrently with MMA warps
        epilogue_branch(sX4, g_Wn4, out, 0, g * 32 + lane, base, n);
        return;
    }

    // ================= MMA warps (0-3): node = warp, full m32n32k128 =================
    const int g = warp;
    const int node = min(base + g, n - 1);

    float acc[2][4][4];
    #pragma unroll
    for (int m = 0; m < 2; ++m)
        #pragma unroll
        for (int nt = 0; nt < 4; ++nt)
            #pragma unroll
            for (int r = 0; r < 4; ++r) acc[m][nt][r] = 0.f;
    {
        const uint32_t AhiU = smem + OFF_AHI + g * ATILE;
        const uint32_t AloU = smem + OFF_ALO + g * ATILE;
        const int lr = lane & 7, seg = lane >> 3;
        const uint32_t aOff = (uint32_t)(((seg & 1) * 8 + lr) * ASTRIDE + (seg >> 1) * 16);

        #pragma unroll
        for (int s = 0; s < 8; ++s) {
            const uint32_t dby = s * 32;
            uint32_t aH[2][4], aL[2][4];
            ldsm4(aH[0][0], aH[0][1], aH[0][2], aH[0][3], AhiU + aOff + dby);
            ldsm4(aH[1][0], aH[1][1], aH[1][2], aH[1][3], AhiU + aOff + 16 * ASTRIDE + dby);
            ldsm4(aL[0][0], aL[0][1], aL[0][2], aL[0][3], AloU + aOff + dby);
            ldsm4(aL[1][0], aL[1][1], aL[1][2], aL[1][3], AloU + aOff + 16 * ASTRIDE + dby);
            uint4 bh0 = g_BfHi[(s * 2)     * 32 + lane];
            uint4 bh1 = g_BfHi[(s * 2 + 1) * 32 + lane];
            uint4 bl0 = g_BfLo[(s * 2)     * 32 + lane];
            uint4 bl1 = g_BfLo[(s * 2 + 1) * 32 + lane];
            #pragma unroll
            for (int m = 0; m < 2; ++m) {
                mma16816(acc[m][0], aH[m][0], aH[m][1], aH[m][2], aH[m][3], bh0.x, bh0.y);
                mma16816(acc[m][0], aH[m][0], aH[m][1], aH[m][2], aH[m][3], bl0.x, bl0.y);
                mma16816(acc[m][0], aL[m][0], aL[m][1], aL[m][2], aL[m][3], bh0.x, bh0.y);
                mma16816(acc[m][1], aH[m][0], aH[m][1], aH[m][2], aH[m][3], bh0.z, bh0.w);
                mma16816(acc[m][1], aH[m][0], aH[m][1], aH[m][2], aH[m][3], bl0.z, bl0.w);
                mma16816(acc[m][1], aL[m][0], aL[m][1], aL[m][2], aL[m][3], bh0.z, bh0.w);
                mma16816(acc[m][2], aH[m][0], aH[m][1], aH[m][2], aH[m][3], bh1.x, bh1.y);
                mma16816(acc[m][2], aH[m][0], aH[m][1], aH[m][2], aH[m][3], bl1.x, bl1.y);
                mma16816(acc[m][2], aL[m][0], aL[m][1], aL[m][2], aL[m][3], bh1.x, bh1.y);
                mma16816(acc[m][3], aH[m][0], aH[m][1], aH[m][2], aH[m][3], bh1.z, bh1.w);
                mma16816(acc[m][3], aH[m][0], aH[m][1], aH[m][2], aH[m][3], bl1.z, bl1.w);
                mma16816(acc[m][3], aL[m][0], aL[m][1], aL[m][2], aL[m][3], bh1.z, bh1.w);
            }
        }
    }

    BAR_SYNC(g + 1, 64);                // wait for u from helper warp g+4

    // ---- scores + softmax, fully in-warp ----
    // acc[m][nt] regs: rows r=lane/4 (+8), cols c0=nt*8+(lane%4)*2 (+1); m adds 16 to rows.
    float w4[4];
    {
        const float* sUg = sU + g * 32;
        const int c0 = (lane & 3) * 2;
        float uu[8];
        #pragma unroll
        for (int nt = 0; nt < 4; ++nt) {
            uu[2 * nt]     = sUg[nt * 8 + c0];
            uu[2 * nt + 1] = sUg[nt * 8 + c0 + 1];
        }
        float p[4];   // rows r, r+8, r+16, r+24
        #pragma unroll
        for (int j = 0; j < 4; ++j) {
            int m = j >> 1, r0 = (j & 1) * 2;
            float s = 0.f;
            #pragma unroll
            for (int nt = 0; nt < 4; ++nt)
                s += ftanh(acc[m][nt][r0]) * uu[2 * nt]
                   + ftanh(acc[m][nt][r0 + 1]) * uu[2 * nt + 1];
            p[j] = s;
        }
        #pragma unroll
        for (int j = 0; j < 4; ++j) {
            p[j] += __shfl_xor_sync(0xffffffffu, p[j], 1);
            p[j] += __shfl_xor_sync(0xffffffffu, p[j], 2);
        }
        float mx = fmaxf(fmaxf(p[0], p[1]), fmaxf(p[2], p[3]));
        #pragma unroll
        for (int o = 4; o <= 16; o <<= 1) mx = fmaxf(mx, __shfl_xor_sync(0xffffffffu, mx, o));
        float S = 0.f;
        #pragma unroll
        for (int j = 0; j < 4; ++j) { w4[j] = __expf(p[j] - mx); S += w4[j]; }
        #pragma unroll
        for (int o = 4; o <= 16; o <<= 1) S += __shfl_xor_sync(0xffffffffu, S, o);
        float iZ = __fdividef(1.0f, S);
        #pragma unroll
        for (int j = 0; j < 4; ++j) w4[j] *= iZ;
    }

    // ---- aggregation: exact fp32 rows straight from global (L1-hot) ----
    {
        const float4* src4 = reinterpret_cast<const float4*>(
                                 neib_feats + (size_t)node * (K * D));
        float4 ag = make_float4(0.f, 0.f, 0.f, 0.f);
        #pragma unroll 8
        for (int k = 0; k < 32; ++k) {
            float wk = __shfl_sync(0xffffffffu, w4[k >> 3], (k & 7) * 4);
            float4 v = src4[k * 32 + lane];
            ag.x += wk * v.x; ag.y += wk * v.y;
            ag.z += wk * v.z; ag.w += wk * v.w;
        }
        sAg[g * 32 + lane] = ag;
    }
    BAR_SYNC(5, 128);                   // warps 0-3: all agg rows visible

    // ---- agg-branch epilogue (warps 0-3, col = g*32+lane) ----
    epilogue_branch(sAg, g_Wb4, out, O, g * 32 + lane, base, n);
}

extern "C" void kernel_launch(void* const* d_in, const int* in_sizes, int n_in,
                              void* d_out, int out_size) {
    const float* node_feats = (const float*)d_in[0];
    const float* neib_feats = (const float*)d_in[1];
    // d_in[2] = node_ids, d_in[3] = neib_ids : unused by the reference computation
    const float* W_att1 = (const float*)d_in[4];
    const float* W_att2 = (const float*)d_in[5];
    const float* W_node = (const float*)d_in[6];
    const float* W_neib = (const float*)d_in[7];

    cudaFuncSetAttribute(attn_agg_mma_kernel,
                         cudaFuncAttributeMaxDynamicSharedMemorySize, SMEM_BYTES);

    int n = in_sizes[0] / D;
    repack_kernel<<<1, 1024>>>(W_att1, W_node, W_neib);
    int blocks = (n + G - 1) / G;
    attn_agg_mma_kernel<<<blocks, NTHREADS, SMEM_BYTES>>>(node_feats, neib_feats,
                                                          W_att2, (float*)d_out, n);
}

// round 17
// speedup vs baseline: 2.3588x; 1.2076x over previous
#include <cuda_runtime.h>
#include <cuda_bf16.h>
#include <cstdint>

typedef unsigned long long u64;

constexpr int D = 128;
constexpr int K = 32;
constexpr int H = 32;
constexpr int O = 128;
constexpr int G = 4;                 // nodes per CTA
constexpr int NTHREADS = 256;

constexpr int ATILE = 32 * 256;      // 8192 B per 32x128 bf16 tile (swizzled, no pad)

// ---- dynamic smem layout (bytes, 16B aligned) ----
constexpr uint32_t OFF_AHI = 0;           // 4 nodes x 8192
constexpr uint32_t OFF_ALO = 32768;       // 4 x 8192
constexpr uint32_t OFF_W2  = 65536;       // 32*33*4 = 4224
constexpr uint32_t OFF_X   = 69760;       // 4*32 float4 = 2048
constexpr uint32_t OFF_AG  = 71808;       // 2048
constexpr uint32_t OFF_U   = 73856;       // 512
constexpr uint32_t OFF_T   = 74368;       // 512
constexpr uint32_t SMEM_BYTES = 74880;    // <= 76K -> 3 CTAs/SM

// ---- persistent repacked weights ----
__device__ ulonglong2 g_W1q[32 * 32];     // fp32-packed W1 (exact u path)
// W1^T bf16 hi/lo as MMA B-fragments: [(s*2+p)*32 + lane] = uint4
__device__ uint4      g_BfHi[8 * 2 * 32];
__device__ uint4      g_BfLo[8 * 2 * 32];
__device__ float4     g_Wn4[32 * 128];    // [q][col] = W_node[4q..4q+3][col]
__device__ float4     g_Wb4[32 * 128];

// ---- helpers ----
__device__ __forceinline__ u64 pack2(float lo, float hi) {
    u64 r; asm("mov.b64 %0, {%1, %2};" : "=l"(r) : "f"(lo), "f"(hi)); return r;
}
__device__ __forceinline__ float2 unpack2(u64 v) {
    float2 f; asm("mov.b64 {%0, %1}, %2;" : "=f"(f.x), "=f"(f.y) : "l"(v)); return f;
}
__device__ __forceinline__ u64 ffma2(u64 a, u64 b, u64 c) {
    u64 d; asm("fma.rn.f32x2 %0, %1, %2, %3;" : "=l"(d) : "l"(a), "l"(b), "l"(c)); return d;
}
__device__ __forceinline__ float fc(const float4& v, int i) {
    return i == 0 ? v.x : (i == 1 ? v.y : (i == 2 ? v.z : v.w));
}
__device__ __forceinline__ uint32_t smem_u32(const void* p) {
    uint32_t a;
    asm("{ .reg .u64 t; cvta.to.shared.u64 t, %1; cvt.u32.u64 %0, t; }" : "=r"(a) : "l"(p));
    return a;
}
__device__ __forceinline__ float ftanh(float x) {
    float e = __expf(2.0f * x);
    return 1.0f - __fdividef(2.0f, e + 1.0f);
}
// 256B-row swizzle: XOR row[2:0] (offset bits [10:8]) into col bits [6:4]
__device__ __forceinline__ uint32_t sw256(uint32_t off) {
    return off ^ ((off >> 4) & 0x70);
}
__device__ __forceinline__ void ldsm4(uint32_t& r0, uint32_t& r1, uint32_t& r2, uint32_t& r3,
                                      uint32_t addr) {
    asm volatile("ldmatrix.sync.aligned.m8n8.x4.shared.b16 {%0,%1,%2,%3}, [%4];"
                 : "=r"(r0), "=r"(r1), "=r"(r2), "=r"(r3) : "r"(addr));
}
__device__ __forceinline__ void mma16816(float* d, uint32_t a0, uint32_t a1, uint32_t a2,
                                         uint32_t a3, uint32_t b0, uint32_t b1) {
    asm volatile("mma.sync.aligned.m16n8k16.row.col.f32.bf16.bf16.f32 "
                 "{%0,%1,%2,%3}, {%4,%5,%6,%7}, {%8,%9}, {%0,%1,%2,%3};"
                 : "+f"(d[0]), "+f"(d[1]), "+f"(d[2]), "+f"(d[3])
                 : "r"(a0), "r"(a1), "r"(a2), "r"(a3), "r"(b0), "r"(b1));
}
#define BAR_SYNC(id, cnt)   asm volatile("bar.sync %0, %1;"   :: "r"(id), "r"(cnt) : "memory")
#define BAR_ARRIVE(id, cnt) asm volatile("bar.arrive %0, %1;" :: "r"(id), "r"(cnt) : "memory")

// ============================ repack (tiny, once per launch) ============================
__device__ __forceinline__ uint32_t pkbf(float a, float b) {
    __nv_bfloat162 t = __floats2bfloat162_rn(a, b);
    return *reinterpret_cast<uint32_t*>(&t);
}

__global__ void repack_kernel(const float* __restrict__ W_att1,
                              const float* __restrict__ W_node,
                              const float* __restrict__ W_neib) {
    int t = threadIdx.x;  // 1024 threads
    if (t < 1024) {       // g_W1q: [q][h] = d-quad packed f32x2 (exact)
        int q = t >> 5, h = t & 31;
        ulonglong2 w;
        w.x = pack2(W_att1[(4 * q) * H + h],     W_att1[(4 * q + 1) * H + h]);
        w.y = pack2(W_att1[(4 * q + 2) * H + h], W_att1[(4 * q + 3) * H + h]);
        g_W1q[t] = w;
    }
    if (t < 512) {        // B fragments (hi + lo)
        int s = t >> 6, p = (t >> 5) & 1, ln = t & 31;
        int k0 = s * 16 + (ln & 3) * 2;
        int hA = (2 * p) * 8 + (ln >> 2);
        int hB = (2 * p + 1) * 8 + (ln >> 2);
        float wh[4][2], wl[4][2];
        int ks[4] = {k0, k0 + 1, k0 + 8, k0 + 9};
        #pragma unroll
        for (int i = 0; i < 4; ++i) {
            float wa = W_att1[ks[i] * H + hA];
            float wb = W_att1[ks[i] * H + hB];
            wh[i][0] = wa; wh[i][1] = wb;
            wl[i][0] = wa - __bfloat162float(__float2bfloat16_rn(wa));
            wl[i][1] = wb - __bfloat162float(__float2bfloat16_rn(wb));
        }
        uint4 hi, lo;
        hi.x = pkbf(wh[0][0], wh[1][0]);  hi.y = pkbf(wh[2][0], wh[3][0]);
        hi.z = pkbf(wh[0][1], wh[1][1]);  hi.w = pkbf(wh[2][1], wh[3][1]);
        lo.x = pkbf(wl[0][0], wl[1][0]);  lo.y = pkbf(wl[2][0], wl[3][0]);
        lo.z = pkbf(wl[0][1], wl[1][1]);  lo.w = pkbf(wl[2][1], wl[3][1]);
        g_BfHi[t] = hi;
        g_BfLo[t] = lo;
    }
    for (int i = t; i < 32 * 128; i += 1024) {
        int q = i >> 7, col = i & 127;
        g_Wn4[i] = make_float4(W_node[(4 * q) * O + col],     W_node[(4 * q + 1) * O + col],
                               W_node[(4 * q + 2) * O + col], W_node[(4 * q + 3) * O + col]);
        g_Wb4[i] = make_float4(W_neib[(4 * q) * O + col],     W_neib[(4 * q + 1) * O + col],
                               W_neib[(4 * q + 2) * O + col], W_neib[(4 * q + 3) * O + col]);
    }
}

// ============================ epilogue helper ============================
__device__ __forceinline__ void epilogue_branch(const float4* __restrict__ src,   // [4][32]
                                                const float4* __restrict__ W4,
                                                float* __restrict__ out,
                                                int colbase, int col, int base, int n) {
    u64 acc01 = 0ull, acc23 = 0ull;
    #pragma unroll 4
    for (int q = 0; q < 32; ++q) {
        float4 wv = W4[q * 128 + col];
        float4 s0 = src[q], s1 = src[32 + q], s2 = src[64 + q], s3 = src[96 + q];
        #pragma unroll
        for (int i = 0; i < 4; ++i) {
            float wf = fc(wv, i);
            u64 w2 = pack2(wf, wf);
            acc01 = ffma2(pack2(fc(s0, i), fc(s1, i)), w2, acc01);
            acc23 = ffma2(pack2(fc(s2, i), fc(s3, i)), w2, acc23);
        }
    }
    float2 f01 = unpack2(acc01), f23 = unpack2(acc23);
    int oc = colbase + col;
    if (base     < n) out[(size_t)(base)     * 256 + oc] = fmaxf(f01.x, 0.f);
    if (base + 1 < n) out[(size_t)(base + 1) * 256 + oc] = fmaxf(f01.y, 0.f);
    if (base + 2 < n) out[(size_t)(base + 2) * 256 + oc] = fmaxf(f23.x, 0.f);
    if (base + 3 < n) out[(size_t)(base + 3) * 256 + oc] = fmaxf(f23.y, 0.f);
}

// ============================ main fused kernel ============================
__global__ __launch_bounds__(NTHREADS, 3)
void attn_agg_mma_kernel(const float* __restrict__ node_feats,
                         const float* __restrict__ neib_feats,
                         const float* __restrict__ W_att2,
                         float* __restrict__ out, int n)
{
    extern __shared__ char dsm[];
    const uint32_t smem = smem_u32(dsm);

    const int tid  = threadIdx.x;
    const int lane = tid & 31;
    const int warp = tid >> 5;         // 0..7

    float*  sW2 = reinterpret_cast<float*>(dsm + OFF_W2);
    float4* sX4 = reinterpret_cast<float4*>(dsm + OFF_X);     // [4][32]
    float4* sAg = reinterpret_cast<float4*>(dsm + OFF_AG);    // [4][32]
    float*  sU  = reinterpret_cast<float*>(dsm + OFF_U);      // [4][32]
    float*  sT  = reinterpret_cast<float*>(dsm + OFF_T);      // [4][32]

    const int base = blockIdx.x * G;

    // ================= phase 1: staging (all 8 warps; pair per node) =================
    {
        const int sg = warp >> 1;       // node staged by this warp pair
        const int hh = warp & 1;        // row-half
        const int snode = min(base + sg, n - 1);
        #pragma unroll
        for (int i = 0; i < 4; ++i) {
            int j = tid + i * NTHREADS;
            sW2[(j >> 5) * 33 + (j & 31)] = W_att2[j];
        }
        if (hh == 0)
            sX4[sg * 32 + lane] =
                reinterpret_cast<const float4*>(node_feats)[(size_t)snode * 32 + lane];
        const float4* src4 = reinterpret_cast<const float4*>(
                                 neib_feats + (size_t)snode * (K * D));
        char* Ahi = dsm + OFF_AHI + sg * ATILE;
        char* Alo = dsm + OFF_ALO + sg * ATILE;
        #pragma unroll 4
        for (int j = 0; j < 16; ++j) {
            int k = hh * 16 + j;
            float4 v = src4[k * 32 + lane];
            __nv_bfloat162 h0 = __floats2bfloat162_rn(v.x, v.y);
            __nv_bfloat162 h1 = __floats2bfloat162_rn(v.z, v.w);
            float2 f0 = __bfloat1622float2(h0);
            float2 f1 = __bfloat1622float2(h1);
            __nv_bfloat162 l0 = __floats2bfloat162_rn(v.x - f0.x, v.y - f0.y);
            __nv_bfloat162 l1 = __floats2bfloat162_rn(v.z - f1.x, v.w - f1.y);
            uint2 hv = make_uint2(*reinterpret_cast<uint32_t*>(&h0),
                                  *reinterpret_cast<uint32_t*>(&h1));
            uint2 lv = make_uint2(*reinterpret_cast<uint32_t*>(&l0),
                                  *reinterpret_cast<uint32_t*>(&l1));
            uint32_t so = sw256((uint32_t)(k * 256 + lane * 8));
            *reinterpret_cast<uint2*>(Ahi + so) = hv;
            *reinterpret_cast<uint2*>(Alo + so) = lv;
        }
    }
    __syncthreads();

    if (warp >= 4) {
        // ================= helper warps: u (once per node) + x-branch epilogue =======
        const int g = warp - 4;
        float* sTg = sT + g * 32;
        {
            const float4* xv4 = sX4 + g * 32;
            u64 a = 0ull;
            #pragma unroll
            for (int q = 0; q < 32; ++q) {
                ulonglong2 w = g_W1q[q * 32 + lane];
                float4 xv = xv4[q];
                a = ffma2(pack2(xv.x, xv.y), w.x, a);
                a = ffma2(pack2(xv.z, xv.w), w.y, a);
            }
            float2 qa = unpack2(a);
            sTg[lane] = tanhf(qa.x + qa.y);
            __syncwarp();
            float na = 0.f;
            #pragma unroll
            for (int h = 0; h < 32; ++h) na += sTg[h] * sW2[h * 33 + lane];
            __syncwarp();
            sTg[lane] = na;
            __syncwarp();
            float u = 0.f;
            #pragma unroll
            for (int h = 0; h < 32; ++h) u += sW2[lane * 33 + h] * sTg[h];
            sU[g * 32 + lane] = u;
        }
        BAR_ARRIVE(g + 1, 64);          // signal u ready; don't block
        // x-branch epilogue runs concurrently with MMA warps
        epilogue_branch(sX4, g_Wn4, out, 0, g * 32 + lane, base, n);
        return;
    }

    // ================= MMA warps (0-3): node = warp, full m32n32k128 =================
    const int g = warp;
    const int node = min(base + g, n - 1);

    float acc[2][4][4];
    #pragma unroll
    for (int m = 0; m < 2; ++m)
        #pragma unroll
        for (int nt = 0; nt < 4; ++nt)
            #pragma unroll
            for (int r = 0; r < 4; ++r) acc[m][nt][r] = 0.f;
    {
        const uint32_t AhiU = smem + OFF_AHI + g * ATILE;
        const uint32_t AloU = smem + OFF_ALO + g * ATILE;
        const int lr = lane & 7, seg = lane >> 3;
        // logical ldsm offset (row part + col-seg); swizzle XOR term is loop-invariant
        const uint32_t aOffL = (uint32_t)(((seg & 1) * 8 + lr) * 256 + (seg >> 1) * 16);
        const uint32_t swx   = (aOffL >> 4) & 0x70;

        #pragma unroll
        for (int s = 0; s < 8; ++s) {
            const uint32_t dby = s * 32;
            const uint32_t o0 = (aOffL + dby) ^ swx;           // rows 0-15
            const uint32_t o1 = (aOffL + 4096 + dby) ^ swx;    // rows 16-31
            uint32_t aH[2][4], aL[2][4];
            ldsm4(aH[0][0], aH[0][1], aH[0][2], aH[0][3], AhiU + o0);
            ldsm4(aH[1][0], aH[1][1], aH[1][2], aH[1][3], AhiU + o1);
            ldsm4(aL[0][0], aL[0][1], aL[0][2], aL[0][3], AloU + o0);
            ldsm4(aL[1][0], aL[1][1], aL[1][2], aL[1][3], AloU + o1);
            uint4 bh0 = g_BfHi[(s * 2)     * 32 + lane];
            uint4 bh1 = g_BfHi[(s * 2 + 1) * 32 + lane];
            uint4 bl0 = g_BfLo[(s * 2)     * 32 + lane];
            uint4 bl1 = g_BfLo[(s * 2 + 1) * 32 + lane];
            #pragma unroll
            for (int m = 0; m < 2; ++m) {
                mma16816(acc[m][0], aH[m][0], aH[m][1], aH[m][2], aH[m][3], bh0.x, bh0.y);
                mma16816(acc[m][0], aH[m][0], aH[m][1], aH[m][2], aH[m][3], bl0.x, bl0.y);
                mma16816(acc[m][0], aL[m][0], aL[m][1], aL[m][2], aL[m][3], bh0.x, bh0.y);
                mma16816(acc[m][1], aH[m][0], aH[m][1], aH[m][2], aH[m][3], bh0.z, bh0.w);
                mma16816(acc[m][1], aH[m][0], aH[m][1], aH[m][2], aH[m][3], bl0.z, bl0.w);
                mma16816(acc[m][1], aL[m][0], aL[m][1], aL[m][2], aL[m][3], bh0.z, bh0.w);
                mma16816(acc[m][2], aH[m][0], aH[m][1], aH[m][2], aH[m][3], bh1.x, bh1.y);
                mma16816(acc[m][2], aH[m][0], aH[m][1], aH[m][2], aH[m][3], bl1.x, bl1.y);
                mma16816(acc[m][2], aL[m][0], aL[m][1], aL[m][2], aL[m][3], bh1.x, bh1.y);
                mma16816(acc[m][3], aH[m][0], aH[m][1], aH[m][2], aH[m][3], bh1.z, bh1.w);
                mma16816(acc[m][3], aH[m][0], aH[m][1], aH[m][2], aH[m][3], bl1.z, bl1.w);
                mma16816(acc[m][3], aL[m][0], aL[m][1], aL[m][2], aL[m][3], bh1.z, bh1.w);
            }
        }
    }

    BAR_SYNC(g + 1, 64);                // wait for u from helper warp g+4

    // ---- scores + softmax, fully in-warp ----
    float w4[4];
    {
        const float* sUg = sU + g * 32;
        const int c0 = (lane & 3) * 2;
        float uu[8];
        #pragma unroll
        for (int nt = 0; nt < 4; ++nt) {
            uu[2 * nt]     = sUg[nt * 8 + c0];
            uu[2 * nt + 1] = sUg[nt * 8 + c0 + 1];
        }
        float p[4];   // rows r, r+8, r+16, r+24
        #pragma unroll
        for (int j = 0; j < 4; ++j) {
            int m = j >> 1, r0 = (j & 1) * 2;
            float s = 0.f;
            #pragma unroll
            for (int nt = 0; nt < 4; ++nt)
                s += ftanh(acc[m][nt][r0]) * uu[2 * nt]
                   + ftanh(acc[m][nt][r0 + 1]) * uu[2 * nt + 1];
            p[j] = s;
        }
        #pragma unroll
        for (int j = 0; j < 4; ++j) {
            p[j] += __shfl_xor_sync(0xffffffffu, p[j], 1);
            p[j] += __shfl_xor_sync(0xffffffffu, p[j], 2);
        }
        float mx = fmaxf(fmaxf(p[0], p[1]), fmaxf(p[2], p[3]));
        #pragma unroll
        for (int o = 4; o <= 16; o <<= 1) mx = fmaxf(mx, __shfl_xor_sync(0xffffffffu, mx, o));
        float S = 0.f;
        #pragma unroll
        for (int j = 0; j < 4; ++j) { w4[j] = __expf(p[j] - mx); S += w4[j]; }
        #pragma unroll
        for (int o = 4; o <= 16; o <<= 1) S += __shfl_xor_sync(0xffffffffu, S, o);
        float iZ = __fdividef(1.0f, S);
        #pragma unroll
        for (int j = 0; j < 4; ++j) w4[j] *= iZ;
    }

    // ---- aggregation: exact fp32 rows straight from global (L1-hot) ----
    {
        const float4* src4 = reinterpret_cast<const float4*>(
                                 neib_feats + (size_t)node * (K * D));
        float4 ag = make_float4(0.f, 0.f, 0.f, 0.f);
        #pragma unroll 8
        for (int k = 0; k < 32; ++k) {
            float wk = __shfl_sync(0xffffffffu, w4[k >> 3], (k & 7) * 4);
            float4 v = src4[k * 32 + lane];
            ag.x += wk * v.x; ag.y += wk * v.y;
            ag.z += wk * v.z; ag.w += wk * v.w;
        }
        sAg[g * 32 + lane] = ag;
    }
    BAR_SYNC(5, 128);                   // warps 0-3: all agg rows visible

    // ---- agg-branch epilogue (warps 0-3, col = g*32+lane) ----
    epilogue_branch(sAg, g_Wb4, out, O, g * 32 + lane, base, n);
}

extern "C" void kernel_launch(void* const* d_in, const int* in_sizes, int n_in,
                              void* d_out, int out_size) {
    const float* node_feats = (const float*)d_in[0];
    const float* neib_feats = (const float*)d_in[1];
    // d_in[2] = node_ids, d_in[3] = neib_ids : unused by the reference computation
    const float* W_att1 = (const float*)d_in[4];
    const float* W_att2 = (const float*)d_in[5];
    const float* W_node = (const float*)d_in[6];
    const float* W_neib = (const float*)d_in[7];

    cudaFuncSetAttribute(attn_agg_mma_kernel,
                         cudaFuncAttributeMaxDynamicSharedMemorySize, SMEM_BYTES);

    int n = in_sizes[0] / D;
    repack_kernel<<<1, 1024>>>(W_att1, W_node, W_neib);
    int blocks = (n + G - 1) / G;
    attn_agg_mma_kernel<<<blocks, NTHREADS, SMEM_BYTES>>>(node_feats, neib_feats,
                                                          W_att2, (float*)d_out, n);
}